// round 5
// baseline (speedup 1.0000x reference)
#include <cuda_runtime.h>
#include <cuda_bf16.h>
#include <cstdint>

#define DI __device__ __forceinline__

namespace {
constexpr int S = 16384;      // tokens = 16*32*32
constexpr int C = 128;        // channels
// (1/sqrt(128)) * log2(e): folded into Q so softmax uses exp2
constexpr float SCALE_LOG2E = 0.08838834764831845f * 1.4426950408889634f;
}

// ---------------- scratch (device globals; no allocs allowed) ----------------
// __align__(128): cp.async 16B needs 16B-aligned global addresses; type-default
// alignment for bf16 arrays is only 2B.
__device__ __align__(128) __nv_bfloat16 g_xn[S * C];
__device__ __align__(128) __nv_bfloat16 g_q [S * C];
__device__ __align__(128) __nv_bfloat16 g_k [S * C];
__device__ __align__(128) __nv_bfloat16 g_v [S * C];
__device__ __align__(128) __nv_bfloat16 g_at[S * C];
__device__ __align__(128) __nv_bfloat16 g_wt[4][C * C];  // wt[n][k] = W[k][n], bf16

// ---------------- small PTX helpers ----------------
DI uint32_t sptr(const void* p) { return (uint32_t)__cvta_generic_to_shared(p); }

DI void cp16(uint32_t s, const void* g) {
    asm volatile("cp.async.cg.shared.global [%0], [%1], 16;\n" :: "r"(s), "l"(g));
}
DI void cp_commit() { asm volatile("cp.async.commit_group;\n" ::: "memory"); }
template<int N> DI void cp_wait() { asm volatile("cp.async.wait_group %0;\n" :: "n"(N) : "memory"); }

// tile layout: rows x 128 bf16 (256B/row, 16 chunks of 16B), XOR-swizzled for
// conflict-free ldmatrix (chunk ^= row&7)
DI uint32_t sw_off(int row, int ch) { return (uint32_t)(row * 256 + ((ch ^ (row & 7)) << 4)); }

DI void ldsm4(uint32_t* r, uint32_t a) {
    asm volatile("ldmatrix.sync.aligned.m8n8.x4.shared.b16 {%0,%1,%2,%3}, [%4];\n"
                 : "=r"(r[0]), "=r"(r[1]), "=r"(r[2]), "=r"(r[3]) : "r"(a));
}
DI void ldsm4t(uint32_t* r, uint32_t a) {
    asm volatile("ldmatrix.sync.aligned.m8n8.x4.trans.shared.b16 {%0,%1,%2,%3}, [%4];\n"
                 : "=r"(r[0]), "=r"(r[1]), "=r"(r[2]), "=r"(r[3]) : "r"(a));
}
DI void mma16816(float* d, const uint32_t* a, const uint32_t* b) {
    asm volatile("mma.sync.aligned.m16n8k16.row.col.f32.bf16.bf16.f32 "
                 "{%0,%1,%2,%3}, {%4,%5,%6,%7}, {%8,%9}, {%0,%1,%2,%3};\n"
                 : "+f"(d[0]), "+f"(d[1]), "+f"(d[2]), "+f"(d[3])
                 : "r"(a[0]), "r"(a[1]), "r"(a[2]), "r"(a[3]), "r"(b[0]), "r"(b[1]));
}
DI uint32_t packbf(float lo, float hi) {
    __nv_bfloat162 t = __floats2bfloat162_rn(lo, hi);
    return *reinterpret_cast<uint32_t*>(&t);
}

// async copy of an [R x 128] bf16 row-major tile into swizzled smem
template<int R, int NT>
DI void load_tile(uint32_t sbase, const __nv_bfloat16* g, int tid) {
#pragma unroll
    for (int i = 0; i < (R * 16) / NT; i++) {
        int idx = tid + i * NT;
        int row = idx >> 4, ch = idx & 15;
        cp16(sbase + sw_off(row, ch), g + row * 128 + ch * 8);
    }
}

// ---------------- 1) RMSNorm -> bf16 xn ----------------
__global__ void __launch_bounds__(256) k_norm(const float* __restrict__ x,
                                              const float* __restrict__ gamma) {
    int token = blockIdx.x * 8 + (threadIdx.x >> 5);
    int lane  = threadIdx.x & 31;
    float4 a = reinterpret_cast<const float4*>(x + token * 128)[lane];
    float ss = a.x * a.x + a.y * a.y + a.z * a.z + a.w * a.w;
#pragma unroll
    for (int m = 16; m; m >>= 1) ss += __shfl_xor_sync(0xffffffffu, ss, m);
    float sc = 11.313708498984761f / (sqrtf(ss) + 1e-8f);   // sqrt(128)/(||x||+eps)
    float4 gv = reinterpret_cast<const float4*>(gamma)[lane];
    __nv_bfloat162* o = reinterpret_cast<__nv_bfloat162*>(g_xn + token * 128) + lane * 2;
    o[0] = __floats2bfloat162_rn(a.x * sc * gv.x, a.y * sc * gv.y);
    o[1] = __floats2bfloat162_rn(a.z * sc * gv.z, a.w * sc * gv.w);
}

// ---------------- 2) weight transpose + bf16 convert ----------------
__global__ void __launch_bounds__(256) k_wconv(const float* __restrict__ wq,
                                               const float* __restrict__ wk,
                                               const float* __restrict__ wv,
                                               const float* __restrict__ wo) {
    const float* src = blockIdx.y == 0 ? wq : blockIdx.y == 1 ? wk
                     : blockIdx.y == 2 ? wv : wo;
    int idx = blockIdx.x * 256 + threadIdx.x;   // over 16384
    int n = idx >> 7, k = idx & 127;
    g_wt[blockIdx.y][idx] = __float2bfloat16(src[k * 128 + n]);   // wt[n][k] = W[k][n]
}

// ---------------- 3) QKV projection GEMM (bf16 mma) ----------------
__global__ void __launch_bounds__(256) k_qkv(const float* __restrict__ bq,
                                             const float* __restrict__ bk,
                                             const float* __restrict__ bv) {
    extern __shared__ char smem[];
    uint32_t sA = sptr(smem);
    uint32_t sB = sA + 128 * 256;
    int which = blockIdx.y;
    int tid = threadIdx.x, wid = tid >> 5, lane = tid & 31;

    load_tile<128, 256>(sA, g_xn + blockIdx.x * 128 * 128, tid);
    load_tile<128, 256>(sB, g_wt[which], tid);
    cp_commit(); cp_wait<0>(); __syncthreads();

    int agrp = lane >> 3, lr = lane & 7;
    int mrow = wid * 16 + lr + ((agrp & 1) << 3);
    float acc[16][4];
#pragma unroll
    for (int i = 0; i < 16; i++) { acc[i][0] = acc[i][1] = acc[i][2] = acc[i][3] = 0.f; }

#pragma unroll
    for (int kk2 = 0; kk2 < 4; kk2++) {
        uint32_t a0[4], a1[4];
        ldsm4(a0, sA + sw_off(mrow, 4 * kk2 +     (agrp >> 1)));
        ldsm4(a1, sA + sw_off(mrow, 4 * kk2 + 2 + (agrp >> 1)));
#pragma unroll
        for (int nt = 0; nt < 16; nt++) {
            uint32_t b[4];
            ldsm4(b, sB + sw_off(nt * 8 + lr, 4 * kk2 + agrp));
            mma16816(acc[nt], a0, b);
            mma16816(acc[nt], a1, b + 2);
        }
    }

    const float* bias = which == 0 ? bq : which == 1 ? bk : bv;
    __nv_bfloat16* out = which == 0 ? g_q : which == 1 ? g_k : g_v;
    float mul = (which == 0) ? SCALE_LOG2E : 1.0f;   // fold softmax scale into Q
    int r0 = blockIdx.x * 128 + wid * 16 + (lane >> 2);
    int cb = (lane & 3) * 2;
#pragma unroll
    for (int nt = 0; nt < 16; nt++) {
        int col = nt * 8 + cb;
        float b0 = bias[col], b1 = bias[col + 1];
        *reinterpret_cast<__nv_bfloat162*>(out + r0 * 128 + col) =
            __floats2bfloat162_rn((acc[nt][0] + b0) * mul, (acc[nt][1] + b1) * mul);
        *reinterpret_cast<__nv_bfloat162*>(out + (r0 + 8) * 128 + col) =
            __floats2bfloat162_rn((acc[nt][2] + b0) * mul, (acc[nt][3] + b1) * mul);
    }
}

// ---------------- 4) frame-causal flash attention ----------------
// Q tile = 64 rows (never straddles a frame -> zero masking), key chunks of 64,
// cp.async double-buffered K/V. Grid launched in DESCENDING frame order so the
// heaviest tiles start in wave 1.
__global__ void __launch_bounds__(128) k_attn() {
    extern __shared__ char smem[];
    uint32_t sQ = sptr(smem);
    uint32_t sKb[2] = { sQ + 16384, sQ + 32768 };
    uint32_t sVb[2] = { sQ + 49152, sQ + 65536 };
    int tid = threadIdx.x, wid = tid >> 5, lane = tid & 31;

    int qt  = (int)gridDim.x - 1 - (int)blockIdx.x;   // heavy tiles first
    int q0  = qt * 64;
    int nch = (((q0 >> 10) + 1) << 4);                // (frame+1)*1024/64 chunks

    // group 0: Q + chunk 0;  group 1: chunk 1
    load_tile<64, 128>(sQ, g_q + q0 * 128, tid);
    load_tile<64, 128>(sKb[0], g_k, tid);
    load_tile<64, 128>(sVb[0], g_v, tid);
    cp_commit();
    if (nch > 1) {
        load_tile<64, 128>(sKb[1], g_k + 64 * 128, tid);
        load_tile<64, 128>(sVb[1], g_v + 64 * 128, tid);
    }
    cp_commit();
    cp_wait<1>();
    __syncthreads();

    int agrp = lane >> 3, lr = lane & 7;
    int mrow = wid * 16 + lr + ((agrp & 1) << 3);
    uint32_t qf[8][4];                                 // Q fragments live in regs
#pragma unroll
    for (int kk = 0; kk < 8; kk++)
        ldsm4(qf[kk], sQ + sw_off(mrow, 2 * kk + (agrp >> 1)));

    float o[16][4];
#pragma unroll
    for (int j = 0; j < 16; j++) { o[j][0] = o[j][1] = o[j][2] = o[j][3] = 0.f; }
    float m0 = -1e30f, m1 = -1e30f, l0 = 0.f, l1 = 0.f;

    for (int c = 0; c < nch; c++) {
        uint32_t kbuf = sKb[c & 1], vbuf = sVb[c & 1];

        // ---- S = Q @ K^T (already in log2 domain) ----
        float s[8][4];
#pragma unroll
        for (int nt = 0; nt < 8; nt++) { s[nt][0] = s[nt][1] = s[nt][2] = s[nt][3] = 0.f; }
#pragma unroll
        for (int kk2 = 0; kk2 < 4; kk2++) {
#pragma unroll
            for (int nt = 0; nt < 8; nt++) {
                uint32_t b[4];
                ldsm4(b, kbuf + sw_off(nt * 8 + lr, 4 * kk2 + agrp));
                mma16816(s[nt], qf[2 * kk2],     b);
                mma16816(s[nt], qf[2 * kk2 + 1], b + 2);
            }
        }

        // ---- online softmax (rows r=lane>>2 and r+8) ----
        float rm0 = s[0][0], rm1 = s[0][2];
#pragma unroll
        for (int nt = 0; nt < 8; nt++) {
            rm0 = fmaxf(rm0, fmaxf(s[nt][0], s[nt][1]));
            rm1 = fmaxf(rm1, fmaxf(s[nt][2], s[nt][3]));
        }
        rm0 = fmaxf(rm0, __shfl_xor_sync(0xffffffffu, rm0, 1));
        rm0 = fmaxf(rm0, __shfl_xor_sync(0xffffffffu, rm0, 2));
        rm1 = fmaxf(rm1, __shfl_xor_sync(0xffffffffu, rm1, 1));
        rm1 = fmaxf(rm1, __shfl_xor_sync(0xffffffffu, rm1, 2));
        float nm0 = fmaxf(m0, rm0), nm1 = fmaxf(m1, rm1);
        float a0 = exp2f(m0 - nm0), a1 = exp2f(m1 - nm1);

        float rs0 = 0.f, rs1 = 0.f;
        uint32_t pf[4][4];                // P repacked as bf16 A-fragments
#pragma unroll
        for (int nt = 0; nt < 8; nt++) {
            float p0 = exp2f(s[nt][0] - nm0);
            float p1 = exp2f(s[nt][1] - nm0);
            float p2 = exp2f(s[nt][2] - nm1);
            float p3 = exp2f(s[nt][3] - nm1);
            rs0 += p0 + p1; rs1 += p2 + p3;
            int kk = nt >> 1;
            if ((nt & 1) == 0) { pf[kk][0] = packbf(p0, p1); pf[kk][1] = packbf(p2, p3); }
            else               { pf[kk][2] = packbf(p0, p1); pf[kk][3] = packbf(p2, p3); }
        }
        rs0 += __shfl_xor_sync(0xffffffffu, rs0, 1);
        rs0 += __shfl_xor_sync(0xffffffffu, rs0, 2);
        rs1 += __shfl_xor_sync(0xffffffffu, rs1, 1);
        rs1 += __shfl_xor_sync(0xffffffffu, rs1, 2);
        l0 = l0 * a0 + rs0;  l1 = l1 * a1 + rs1;
        m0 = nm0;  m1 = nm1;

#pragma unroll
        for (int j = 0; j < 16; j++) {
            o[j][0] *= a0; o[j][1] *= a0; o[j][2] *= a1; o[j][3] *= a1;
        }

        // ---- O += P @ V (V via ldmatrix.trans) ----
#pragma unroll
        for (int kk2 = 0; kk2 < 2; kk2++) {
#pragma unroll
            for (int j = 0; j < 16; j++) {
                uint32_t b[4];
                ldsm4t(b, vbuf + sw_off(kk2 * 32 + agrp * 8 + lr, j));
                mma16816(o[j], pf[2 * kk2],     b);
                mma16816(o[j], pf[2 * kk2 + 1], b + 2);
            }
        }

        __syncthreads();                    // everyone done with bufs of chunk c
        if (c + 2 < nch) {                  // refill this parity's buffers
            load_tile<64, 128>(sKb[c & 1], g_k + (c + 2) * 64 * 128, tid);
            load_tile<64, 128>(sVb[c & 1], g_v + (c + 2) * 64 * 128, tid);
        }
        cp_commit();
        cp_wait<1>();                       // chunk c+1 is now resident
        __syncthreads();
    }

    // ---- normalize + store bf16 ----
    float i0 = 1.f / l0, i1 = 1.f / l1;
    int r0 = q0 + wid * 16 + (lane >> 2);
    int cb = (lane & 3) * 2;
#pragma unroll
    for (int j = 0; j < 16; j++) {
        int col = j * 8 + cb;
        *reinterpret_cast<__nv_bfloat162*>(g_at + r0 * 128 + col) =
            __floats2bfloat162_rn(o[j][0] * i0, o[j][1] * i0);
        *reinterpret_cast<__nv_bfloat162*>(g_at + (r0 + 8) * 128 + col) =
            __floats2bfloat162_rn(o[j][2] * i1, o[j][3] * i1);
    }
}

// ---------------- 5) output projection + bias + residual ----------------
__global__ void __launch_bounds__(256) k_oproj(const float* __restrict__ bo,
                                               const float* __restrict__ x,
                                               float* __restrict__ out) {
    extern __shared__ char smem[];
    uint32_t sA = sptr(smem);
    uint32_t sB = sA + 128 * 256;
    int tid = threadIdx.x, wid = tid >> 5, lane = tid & 31;

    load_tile<128, 256>(sA, g_at + blockIdx.x * 128 * 128, tid);
    load_tile<128, 256>(sB, g_wt[3], tid);
    cp_commit(); cp_wait<0>(); __syncthreads();

    int agrp = lane >> 3, lr = lane & 7;
    int mrow = wid * 16 + lr + ((agrp & 1) << 3);
    float acc[16][4];
#pragma unroll
    for (int i = 0; i < 16; i++) { acc[i][0] = acc[i][1] = acc[i][2] = acc[i][3] = 0.f; }

#pragma unroll
    for (int kk2 = 0; kk2 < 4; kk2++) {
        uint32_t a0[4], a1[4];
        ldsm4(a0, sA + sw_off(mrow, 4 * kk2 +     (agrp >> 1)));
        ldsm4(a1, sA + sw_off(mrow, 4 * kk2 + 2 + (agrp >> 1)));
#pragma unroll
        for (int nt = 0; nt < 16; nt++) {
            uint32_t b[4];
            ldsm4(b, sB + sw_off(nt * 8 + lr, 4 * kk2 + agrp));
            mma16816(acc[nt], a0, b);
            mma16816(acc[nt], a1, b + 2);
        }
    }

    int r0 = blockIdx.x * 128 + wid * 16 + (lane >> 2);
    int cb = (lane & 3) * 2;
#pragma unroll
    for (int nt = 0; nt < 16; nt++) {
        int col = nt * 8 + cb;
        float b0 = bo[col], b1 = bo[col + 1];
        float2 v01 = make_float2(acc[nt][0] + b0 + x[r0 * 128 + col],
                                 acc[nt][1] + b1 + x[r0 * 128 + col + 1]);
        float2 v23 = make_float2(acc[nt][2] + b0 + x[(r0 + 8) * 128 + col],
                                 acc[nt][3] + b1 + x[(r0 + 8) * 128 + col + 1]);
        *reinterpret_cast<float2*>(out + r0 * 128 + col) = v01;
        *reinterpret_cast<float2*>(out + (r0 + 8) * 128 + col) = v23;
    }
}

// ---------------- launch ----------------
extern "C" void kernel_launch(void* const* d_in, const int* in_sizes, int n_in,
                              void* d_out, int out_size) {
    (void)in_sizes; (void)n_in; (void)out_size;
    const float* x     = (const float*)d_in[0];
    const float* gamma = (const float*)d_in[1];
    const float* wq    = (const float*)d_in[2];
    const float* bq    = (const float*)d_in[3];
    const float* wk    = (const float*)d_in[4];
    const float* bk    = (const float*)d_in[5];
    const float* wv    = (const float*)d_in[6];
    const float* bv    = (const float*)d_in[7];
    const float* wo    = (const float*)d_in[8];
    const float* bo    = (const float*)d_in[9];
    float* out = (float*)d_out;

    cudaFuncSetAttribute(k_qkv,   cudaFuncAttributeMaxDynamicSharedMemorySize, 65536);
    cudaFuncSetAttribute(k_oproj, cudaFuncAttributeMaxDynamicSharedMemorySize, 65536);
    cudaFuncSetAttribute(k_attn,  cudaFuncAttributeMaxDynamicSharedMemorySize, 81920);

    k_norm <<<S / 8, 256>>>(x, gamma);
    k_wconv<<<dim3(64, 4), 256>>>(wq, wk, wv, wo);
    k_qkv  <<<dim3(S / 128, 3), 256, 65536>>>(bq, bk, bv);
    k_attn <<<S / 64, 128, 81920>>>();
    k_oproj<<<S / 128, 256, 65536>>>(bo, x, out);
}

// round 6
// speedup vs baseline: 1.6817x; 1.6817x over previous
#include <cuda_runtime.h>
#include <cuda_bf16.h>
#include <cstdint>

#define DI __device__ __forceinline__

namespace {
constexpr int S = 16384;      // tokens = 16*32*32
constexpr int C = 128;        // channels
constexpr int NUNITS = 1152;  // split-KV work units
// (1/sqrt(128)) * log2(e): folded into Q so softmax uses exp2
constexpr float SCALE_LOG2E = 0.08838834764831845f * 1.4426950408889634f;
}

// cumulative split-KV units per frame: frame f has 16 tiles * ceil((f+1)/2) splits
__constant__ int cFCUM[17] = {0,16,32,64,96,144,192,256,320,400,480,576,672,784,896,1024,1152};

// ---------------- scratch (device globals; no allocs allowed) ----------------
__device__ __align__(128) __nv_bfloat16 g_xn[S * C];
__device__ __align__(128) __nv_bfloat16 g_q [S * C];
__device__ __align__(128) __nv_bfloat16 g_k [S * C];
__device__ __align__(128) __nv_bfloat16 g_v [S * C];
__device__ __align__(128) __nv_bfloat16 g_at[S * C];
__device__ __align__(128) __nv_bfloat16 g_wt[4][C * C];  // wt[n][k] = W[k][n], bf16
__device__ __align__(128) float g_po [NUNITS * 64 * 128]; // unnormalized partial O
__device__ __align__(128) float g_pml[NUNITS * 64 * 2];   // per-row {m, l}

// ---------------- small PTX helpers ----------------
DI uint32_t sptr(const void* p) { return (uint32_t)__cvta_generic_to_shared(p); }

DI void cp16(uint32_t s, const void* g) {
    asm volatile("cp.async.cg.shared.global [%0], [%1], 16;\n" :: "r"(s), "l"(g));
}
DI void cp_commit() { asm volatile("cp.async.commit_group;\n" ::: "memory"); }
template<int N> DI void cp_wait() { asm volatile("cp.async.wait_group %0;\n" :: "n"(N) : "memory"); }

// tile layout: rows x 128 bf16 (256B/row, 16 chunks of 16B), XOR-swizzled for
// conflict-free ldmatrix (chunk ^= row&7)
DI uint32_t sw_off(int row, int ch) { return (uint32_t)(row * 256 + ((ch ^ (row & 7)) << 4)); }

DI void ldsm4(uint32_t* r, uint32_t a) {
    asm volatile("ldmatrix.sync.aligned.m8n8.x4.shared.b16 {%0,%1,%2,%3}, [%4];\n"
                 : "=r"(r[0]), "=r"(r[1]), "=r"(r[2]), "=r"(r[3]) : "r"(a));
}
DI void ldsm4t(uint32_t* r, uint32_t a) {
    asm volatile("ldmatrix.sync.aligned.m8n8.x4.trans.shared.b16 {%0,%1,%2,%3}, [%4];\n"
                 : "=r"(r[0]), "=r"(r[1]), "=r"(r[2]), "=r"(r[3]) : "r"(a));
}
DI void mma16816(float* d, const uint32_t* a, const uint32_t* b) {
    asm volatile("mma.sync.aligned.m16n8k16.row.col.f32.bf16.bf16.f32 "
                 "{%0,%1,%2,%3}, {%4,%5,%6,%7}, {%8,%9}, {%0,%1,%2,%3};\n"
                 : "+f"(d[0]), "+f"(d[1]), "+f"(d[2]), "+f"(d[3])
                 : "r"(a[0]), "r"(a[1]), "r"(a[2]), "r"(a[3]), "r"(b[0]), "r"(b[1]));
}
DI uint32_t packbf(float lo, float hi) {
    __nv_bfloat162 t = __floats2bfloat162_rn(lo, hi);
    return *reinterpret_cast<uint32_t*>(&t);
}

// async copy of an [R x 128] bf16 row-major tile into swizzled smem
template<int R, int NT>
DI void load_tile(uint32_t sbase, const __nv_bfloat16* g, int tid) {
#pragma unroll
    for (int i = 0; i < (R * 16) / NT; i++) {
        int idx = tid + i * NT;
        int row = idx >> 4, ch = idx & 15;
        cp16(sbase + sw_off(row, ch), g + row * 128 + ch * 8);
    }
}

// ---------------- 1) RMSNorm -> bf16 xn ----------------
__global__ void __launch_bounds__(256) k_norm(const float* __restrict__ x,
                                              const float* __restrict__ gamma) {
    int token = blockIdx.x * 8 + (threadIdx.x >> 5);
    int lane  = threadIdx.x & 31;
    float4 a = reinterpret_cast<const float4*>(x + token * 128)[lane];
    float ss = a.x * a.x + a.y * a.y + a.z * a.z + a.w * a.w;
#pragma unroll
    for (int m = 16; m; m >>= 1) ss += __shfl_xor_sync(0xffffffffu, ss, m);
    float sc = 11.313708498984761f / (sqrtf(ss) + 1e-8f);   // sqrt(128)/(||x||+eps)
    float4 gv = reinterpret_cast<const float4*>(gamma)[lane];
    __nv_bfloat162* o = reinterpret_cast<__nv_bfloat162*>(g_xn + token * 128) + lane * 2;
    o[0] = __floats2bfloat162_rn(a.x * sc * gv.x, a.y * sc * gv.y);
    o[1] = __floats2bfloat162_rn(a.z * sc * gv.z, a.w * sc * gv.w);
}

// ---------------- 2) weight transpose + bf16 convert ----------------
__global__ void __launch_bounds__(256) k_wconv(const float* __restrict__ wq,
                                               const float* __restrict__ wk,
                                               const float* __restrict__ wv,
                                               const float* __restrict__ wo) {
    const float* src = blockIdx.y == 0 ? wq : blockIdx.y == 1 ? wk
                     : blockIdx.y == 2 ? wv : wo;
    int idx = blockIdx.x * 256 + threadIdx.x;   // over 16384
    int n = idx >> 7, k = idx & 127;
    g_wt[blockIdx.y][idx] = __float2bfloat16(src[k * 128 + n]);   // wt[n][k] = W[k][n]
}

// ---------------- 3) QKV projection GEMM (bf16 mma) ----------------
__global__ void __launch_bounds__(256) k_qkv(const float* __restrict__ bq,
                                             const float* __restrict__ bk,
                                             const float* __restrict__ bv) {
    extern __shared__ char smem[];
    uint32_t sA = sptr(smem);
    uint32_t sB = sA + 128 * 256;
    int which = blockIdx.y;
    int tid = threadIdx.x, wid = tid >> 5, lane = tid & 31;

    load_tile<128, 256>(sA, g_xn + blockIdx.x * 128 * 128, tid);
    load_tile<128, 256>(sB, g_wt[which], tid);
    cp_commit(); cp_wait<0>(); __syncthreads();

    int agrp = lane >> 3, lr = lane & 7;
    int mrow = wid * 16 + lr + ((agrp & 1) << 3);
    float acc[16][4];
#pragma unroll
    for (int i = 0; i < 16; i++) { acc[i][0] = acc[i][1] = acc[i][2] = acc[i][3] = 0.f; }

#pragma unroll
    for (int kk2 = 0; kk2 < 4; kk2++) {
        uint32_t a0[4], a1[4];
        ldsm4(a0, sA + sw_off(mrow, 4 * kk2 +     (agrp >> 1)));
        ldsm4(a1, sA + sw_off(mrow, 4 * kk2 + 2 + (agrp >> 1)));
#pragma unroll
        for (int nt = 0; nt < 16; nt++) {
            uint32_t b[4];
            ldsm4(b, sB + sw_off(nt * 8 + lr, 4 * kk2 + agrp));
            mma16816(acc[nt], a0, b);
            mma16816(acc[nt], a1, b + 2);
        }
    }

    const float* bias = which == 0 ? bq : which == 1 ? bk : bv;
    __nv_bfloat16* out = which == 0 ? g_q : which == 1 ? g_k : g_v;
    float mul = (which == 0) ? SCALE_LOG2E : 1.0f;   // fold softmax scale into Q
    int r0 = blockIdx.x * 128 + wid * 16 + (lane >> 2);
    int cb = (lane & 3) * 2;
#pragma unroll
    for (int nt = 0; nt < 16; nt++) {
        int col = nt * 8 + cb;
        float b0 = bias[col], b1 = bias[col + 1];
        *reinterpret_cast<__nv_bfloat162*>(out + r0 * 128 + col) =
            __floats2bfloat162_rn((acc[nt][0] + b0) * mul, (acc[nt][1] + b1) * mul);
        *reinterpret_cast<__nv_bfloat162*>(out + (r0 + 8) * 128 + col) =
            __floats2bfloat162_rn((acc[nt][2] + b0) * mul, (acc[nt][3] + b1) * mul);
    }
}

// ---------------- 4) split-KV frame-causal flash attention ----------------
// Work unit u = (64-row Q-tile, <=32-chunk key span). 3-stage cp.async ring,
// ONE __syncthreads per chunk, partial (O, m, l) written to scratch.
// Units enumerated heavy-frame-first.
__global__ void __launch_bounds__(128, 2) k_attn() {
    extern __shared__ char smem[];
    uint32_t sQ = sptr(smem);
    uint32_t sK[3], sV[3];
#pragma unroll
    for (int st = 0; st < 3; st++) {
        sK[st] = sQ + 16384 + st * 32768;
        sV[st] = sK[st] + 16384;
    }
    int tid = threadIdx.x, wid = tid >> 5, lane = tid & 31;

    // decode unit (reverse order -> frame 15 first)
    int u = NUNITS - 1 - (int)blockIdx.x;
    int f = 0;
#pragma unroll
    for (int i = 0; i < 16; i++) if (u >= cFCUM[i + 1]) f = i + 1;
    int r   = u - cFCUM[f];
    int ns  = (f >> 1) + 1;            // splits per tile in this frame
    int tif = r / ns;
    int s   = r - tif * ns;
    int q0  = (f * 16 + tif) * 64;
    int kc0 = s * 32;                                  // chunks of 64 keys
    int kc1 = min(kc0 + 32, (f + 1) * 16);
    int nc  = kc1 - kc0;

    // prologue: group 0 = Q + chunk kc0, group 1 = chunk kc0+1
    load_tile<64, 128>(sQ, g_q + q0 * 128, tid);
    load_tile<64, 128>(sK[0], g_k + kc0 * 64 * 128, tid);
    load_tile<64, 128>(sV[0], g_v + kc0 * 64 * 128, tid);
    cp_commit();
    if (nc > 1) {
        load_tile<64, 128>(sK[1], g_k + (kc0 + 1) * 64 * 128, tid);
        load_tile<64, 128>(sV[1], g_v + (kc0 + 1) * 64 * 128, tid);
    }
    cp_commit();

    int agrp = lane >> 3, lr = lane & 7;
    int mrow = wid * 16 + lr + ((agrp & 1) << 3);
    uint32_t qf[8][4];

    float o[16][4];
#pragma unroll
    for (int j = 0; j < 16; j++) { o[j][0] = o[j][1] = o[j][2] = o[j][3] = 0.f; }
    float m0 = -1e30f, m1 = -1e30f, l0 = 0.f, l1 = 0.f;

    for (int i = 0; i < nc; i++) {
        cp_wait<1>();                 // chunk i resident (my part)
        __syncthreads();              // everyone's part; buf (i+2)%3 free
        if (i + 2 < nc) {
            int st = (i + 2) % 3;
            load_tile<64, 128>(sK[st], g_k + (kc0 + i + 2) * 64 * 128, tid);
            load_tile<64, 128>(sV[st], g_v + (kc0 + i + 2) * 64 * 128, tid);
        }
        cp_commit();
        if (i == 0) {
#pragma unroll
            for (int kk = 0; kk < 8; kk++)
                ldsm4(qf[kk], sQ + sw_off(mrow, 2 * kk + (agrp >> 1)));
        }
        uint32_t kbuf = sK[i % 3], vbuf = sV[i % 3];

        // ---- S = Q @ K^T (log2 domain) ----
        float sc[8][4];
#pragma unroll
        for (int nt = 0; nt < 8; nt++) { sc[nt][0] = sc[nt][1] = sc[nt][2] = sc[nt][3] = 0.f; }
#pragma unroll
        for (int kk2 = 0; kk2 < 4; kk2++) {
#pragma unroll
            for (int nt = 0; nt < 8; nt++) {
                uint32_t b[4];
                ldsm4(b, kbuf + sw_off(nt * 8 + lr, 4 * kk2 + agrp));
                mma16816(sc[nt], qf[2 * kk2],     b);
                mma16816(sc[nt], qf[2 * kk2 + 1], b + 2);
            }
        }

        // ---- online softmax (rows lane>>2 and +8) ----
        float rm0 = sc[0][0], rm1 = sc[0][2];
#pragma unroll
        for (int nt = 0; nt < 8; nt++) {
            rm0 = fmaxf(rm0, fmaxf(sc[nt][0], sc[nt][1]));
            rm1 = fmaxf(rm1, fmaxf(sc[nt][2], sc[nt][3]));
        }
        rm0 = fmaxf(rm0, __shfl_xor_sync(0xffffffffu, rm0, 1));
        rm0 = fmaxf(rm0, __shfl_xor_sync(0xffffffffu, rm0, 2));
        rm1 = fmaxf(rm1, __shfl_xor_sync(0xffffffffu, rm1, 1));
        rm1 = fmaxf(rm1, __shfl_xor_sync(0xffffffffu, rm1, 2));
        float nm0 = fmaxf(m0, rm0), nm1 = fmaxf(m1, rm1);
        float a0 = exp2f(m0 - nm0), a1 = exp2f(m1 - nm1);

        float rs0 = 0.f, rs1 = 0.f;
        uint32_t pf[4][4];                // P repacked as bf16 A-fragments
#pragma unroll
        for (int nt = 0; nt < 8; nt++) {
            float p0 = exp2f(sc[nt][0] - nm0);
            float p1 = exp2f(sc[nt][1] - nm0);
            float p2 = exp2f(sc[nt][2] - nm1);
            float p3 = exp2f(sc[nt][3] - nm1);
            rs0 += p0 + p1; rs1 += p2 + p3;
            int kk = nt >> 1;
            if ((nt & 1) == 0) { pf[kk][0] = packbf(p0, p1); pf[kk][1] = packbf(p2, p3); }
            else               { pf[kk][2] = packbf(p0, p1); pf[kk][3] = packbf(p2, p3); }
        }
        rs0 += __shfl_xor_sync(0xffffffffu, rs0, 1);
        rs0 += __shfl_xor_sync(0xffffffffu, rs0, 2);
        rs1 += __shfl_xor_sync(0xffffffffu, rs1, 1);
        rs1 += __shfl_xor_sync(0xffffffffu, rs1, 2);
        l0 = l0 * a0 + rs0;  l1 = l1 * a1 + rs1;
        m0 = nm0;  m1 = nm1;

#pragma unroll
        for (int j = 0; j < 16; j++) {
            o[j][0] *= a0; o[j][1] *= a0; o[j][2] *= a1; o[j][3] *= a1;
        }

        // ---- O += P @ V (V via ldmatrix.trans) ----
#pragma unroll
        for (int kk2 = 0; kk2 < 2; kk2++) {
#pragma unroll
            for (int j = 0; j < 16; j++) {
                uint32_t b[4];
                ldsm4t(b, vbuf + sw_off(kk2 * 32 + agrp * 8 + lr, j));
                mma16816(o[j], pf[2 * kk2],     b);
                mma16816(o[j], pf[2 * kk2 + 1], b + 2);
            }
        }
    }

    // ---- store UNNORMALIZED partial O + per-row (m, l) ----
    int lr0 = wid * 16 + (lane >> 2);
    int cb  = (lane & 3) * 2;
    float* po = g_po + (size_t)u * 8192;
#pragma unroll
    for (int j = 0; j < 16; j++) {
        int col = j * 8 + cb;
        *reinterpret_cast<float2*>(po + lr0 * 128 + col)       = make_float2(o[j][0], o[j][1]);
        *reinterpret_cast<float2*>(po + (lr0 + 8) * 128 + col) = make_float2(o[j][2], o[j][3]);
    }
    if ((lane & 3) == 0) {
        *reinterpret_cast<float2*>(g_pml + u * 128 + lr0 * 2)       = make_float2(m0, l0);
        *reinterpret_cast<float2*>(g_pml + u * 128 + (lr0 + 8) * 2) = make_float2(m1, l1);
    }
}

// ---------------- 4b) split-KV combine ----------------
// One block per 64-row Q-tile; merges its ns partials -> g_at (bf16).
__global__ void __launch_bounds__(256) k_comb() {
    int t  = blockIdx.x;
    int f  = t >> 4;
    int ns = (f >> 1) + 1;
    int ub = cFCUM[f] + (t & 15) * ns;
    int row = threadIdx.x >> 2;
    int c0  = (threadIdx.x & 3) * 32;

    float2 ml[8];
    float m = -1e30f;
    for (int s = 0; s < ns; s++) {
        ml[s] = *reinterpret_cast<const float2*>(g_pml + (ub + s) * 128 + row * 2);
        m = fmaxf(m, ml[s].x);
    }
    float w[8]; float l = 0.f;
    for (int s = 0; s < ns; s++) { w[s] = exp2f(ml[s].x - m); l += w[s] * ml[s].y; }
    float inv = 1.f / l;

    float4 acc[8];
#pragma unroll
    for (int j = 0; j < 8; j++) acc[j] = make_float4(0.f, 0.f, 0.f, 0.f);
    for (int s = 0; s < ns; s++) {
        const float4* p = reinterpret_cast<const float4*>(
            g_po + (size_t)(ub + s) * 8192 + row * 128 + c0);
        float ws = w[s];
#pragma unroll
        for (int j = 0; j < 8; j++) {
            float4 v = p[j];
            acc[j].x += ws * v.x; acc[j].y += ws * v.y;
            acc[j].z += ws * v.z; acc[j].w += ws * v.w;
        }
    }
    __nv_bfloat162* dst = reinterpret_cast<__nv_bfloat162*>(g_at + (t * 64 + row) * 128 + c0);
#pragma unroll
    for (int j = 0; j < 8; j++) {
        dst[2 * j]     = __floats2bfloat162_rn(acc[j].x * inv, acc[j].y * inv);
        dst[2 * j + 1] = __floats2bfloat162_rn(acc[j].z * inv, acc[j].w * inv);
    }
}

// ---------------- 5) output projection + bias + residual ----------------
__global__ void __launch_bounds__(256) k_oproj(const float* __restrict__ bo,
                                               const float* __restrict__ x,
                                               float* __restrict__ out) {
    extern __shared__ char smem[];
    uint32_t sA = sptr(smem);
    uint32_t sB = sA + 128 * 256;
    int tid = threadIdx.x, wid = tid >> 5, lane = tid & 31;

    load_tile<128, 256>(sA, g_at + blockIdx.x * 128 * 128, tid);
    load_tile<128, 256>(sB, g_wt[3], tid);
    cp_commit(); cp_wait<0>(); __syncthreads();

    int agrp = lane >> 3, lr = lane & 7;
    int mrow = wid * 16 + lr + ((agrp & 1) << 3);
    float acc[16][4];
#pragma unroll
    for (int i = 0; i < 16; i++) { acc[i][0] = acc[i][1] = acc[i][2] = acc[i][3] = 0.f; }

#pragma unroll
    for (int kk2 = 0; kk2 < 4; kk2++) {
        uint32_t a0[4], a1[4];
        ldsm4(a0, sA + sw_off(mrow, 4 * kk2 +     (agrp >> 1)));
        ldsm4(a1, sA + sw_off(mrow, 4 * kk2 + 2 + (agrp >> 1)));
#pragma unroll
        for (int nt = 0; nt < 16; nt++) {
            uint32_t b[4];
            ldsm4(b, sB + sw_off(nt * 8 + lr, 4 * kk2 + agrp));
            mma16816(acc[nt], a0, b);
            mma16816(acc[nt], a1, b + 2);
        }
    }

    int r0 = blockIdx.x * 128 + wid * 16 + (lane >> 2);
    int cb = (lane & 3) * 2;
#pragma unroll
    for (int nt = 0; nt < 16; nt++) {
        int col = nt * 8 + cb;
        float b0 = bo[col], b1 = bo[col + 1];
        float2 v01 = make_float2(acc[nt][0] + b0 + x[r0 * 128 + col],
                                 acc[nt][1] + b1 + x[r0 * 128 + col + 1]);
        float2 v23 = make_float2(acc[nt][2] + b0 + x[(r0 + 8) * 128 + col],
                                 acc[nt][3] + b1 + x[(r0 + 8) * 128 + col + 1]);
        *reinterpret_cast<float2*>(out + r0 * 128 + col) = v01;
        *reinterpret_cast<float2*>(out + (r0 + 8) * 128 + col) = v23;
    }
}

// ---------------- launch ----------------
extern "C" void kernel_launch(void* const* d_in, const int* in_sizes, int n_in,
                              void* d_out, int out_size) {
    (void)in_sizes; (void)n_in; (void)out_size;
    const float* x     = (const float*)d_in[0];
    const float* gamma = (const float*)d_in[1];
    const float* wq    = (const float*)d_in[2];
    const float* bq    = (const float*)d_in[3];
    const float* wk    = (const float*)d_in[4];
    const float* bk    = (const float*)d_in[5];
    const float* wv    = (const float*)d_in[6];
    const float* bv    = (const float*)d_in[7];
    const float* wo    = (const float*)d_in[8];
    const float* bo    = (const float*)d_in[9];
    float* out = (float*)d_out;

    cudaFuncSetAttribute(k_qkv,   cudaFuncAttributeMaxDynamicSharedMemorySize, 65536);
    cudaFuncSetAttribute(k_oproj, cudaFuncAttributeMaxDynamicSharedMemorySize, 65536);
    cudaFuncSetAttribute(k_attn,  cudaFuncAttributeMaxDynamicSharedMemorySize, 114688);

    k_norm <<<S / 8, 256>>>(x, gamma);
    k_wconv<<<dim3(64, 4), 256>>>(wq, wk, wv, wo);
    k_qkv  <<<dim3(S / 128, 3), 256, 65536>>>(bq, bk, bv);
    k_attn <<<NUNITS, 128, 114688>>>();
    k_comb <<<S / 64, 256>>>();
    k_oproj<<<S / 128, 256, 65536>>>(bo, x, out);
}